// round 13
// baseline (speedup 1.0000x reference)
#include <cuda_runtime.h>

#define NB 2
#define NS 2048
#define ND 1024
#define NH 16
#define DKH 64
#define QR 6
#define RK 2
#define NT (NB * NS)

__device__ float g_Aq[NT * 96];
__device__ float g_Bq[NT * 384];
__device__ float g_Ak[NT * 32];
__device__ float g_Bk[NT * 128];
__device__ float g_Av[NT * 32];
__device__ float g_Bv[NT * 128];
__device__ float g_qh[(size_t)NB * NH * NS * DKH];
__device__ float g_kh[(size_t)NB * NH * NS * DKH];
__device__ float g_vh[(size_t)NB * NH * NS * DKH];   // (b,h,s,d)
__device__ float g_vhT[(size_t)NB * NH * DKH * NS];  // (b,h,d,s)
__device__ float g_att[(size_t)NT * ND];

__device__ __forceinline__ float to_tf32(float x) {
    asm("cvt.rna.tf32.f32 %0, %0;" : "+f"(x));
    return x;
}
__device__ __forceinline__ float ex2(float x) {
    asm("ex2.approx.f32 %0, %0;" : "+f"(x));
    return x;
}
__device__ __forceinline__ unsigned fu(float x) { return __float_as_uint(x); }

__device__ __forceinline__ void mma8(float* c, const unsigned* a, const unsigned* b) {
    asm("mma.sync.aligned.m16n8k8.row.col.f32.tf32.tf32.f32 "
        "{%0,%1,%2,%3},{%4,%5,%6,%7},{%8,%9},{%0,%1,%2,%3};"
        : "+f"(c[0]), "+f"(c[1]), "+f"(c[2]), "+f"(c[3])
        : "r"(a[0]), "r"(a[1]), "r"(a[2]), "r"(a[3]), "r"(b[0]), "r"(b[1]));
}

__device__ __forceinline__ void ldsm4(unsigned* r, const float* p) {
    unsigned a = (unsigned)__cvta_generic_to_shared(p);
    asm volatile("ldmatrix.sync.aligned.m8n8.x4.shared.b16 {%0,%1,%2,%3},[%4];"
                 : "=r"(r[0]), "=r"(r[1]), "=r"(r[2]), "=r"(r[3]) : "r"(a));
}

__device__ __forceinline__ void cpa16(float* s, const float* g) {
    unsigned sa = (unsigned)__cvta_generic_to_shared(s);
    asm volatile("cp.async.cg.shared.global [%0],[%1],16;" ::"r"(sa), "l"(g));
}
#define CP_COMMIT() asm volatile("cp.async.commit_group;")
#define CP_WAIT0() asm volatile("cp.async.wait_group 0;" ::: "memory")

// ---------------------------------------------------------------------------
// tf32 GEMM: C[m0:+128, n0:+128] = X[M,K]*W[K,N]. 8 warps (2m x 4n),
// warp tile 64x32, BK=16, ldmatrix A-frags, double-buffered smem.
// ---------------------------------------------------------------------------
#define GXS 20
#define GWS 136

__device__ __forceinline__ void gemm3(const float* __restrict__ X,
                                      const float* __restrict__ W,
                                      float* __restrict__ C, int N, int K,
                                      int m0, int n0) {
    __shared__ float Xs[2][128 * GXS];
    __shared__ float Ws[2][16 * GWS];
    const int tid = threadIdx.x, lane = tid & 31, wid = tid >> 5;
    const int g = lane >> 2, qd = lane & 3;
    const int wm = (wid & 1) * 64, wn = (wid >> 1) * 32;
    const int ar = (lane & 7) + ((lane >> 3) & 1) * 8, ac = (lane >> 4) * 4;

    const int fm = tid >> 1, fh = (tid & 1) * 8;
    const int fk = tid >> 5, fn = (tid & 31) * 4;
    const bool wok = (n0 + fn) < N;
    const float* Xr = X + (size_t)(m0 + fm) * K + fh;
    const float* Wr = W + (size_t)fk * N + n0 + fn;

    float acc[4][4][4];
#pragma unroll
    for (int mt = 0; mt < 4; mt++)
#pragma unroll
        for (int nt = 0; nt < 4; nt++)
#pragma unroll
            for (int j = 0; j < 4; j++) acc[mt][nt][j] = 0.f;

    const float4 z4 = make_float4(0.f, 0.f, 0.f, 0.f);
    float4 xa0 = *(const float4*)&Xr[0];
    float4 xa1 = *(const float4*)&Xr[4];
    float4 wa0 = wok ? *(const float4*)&Wr[0] : z4;
    float4 wa1 = wok ? *(const float4*)&Wr[(size_t)8 * N] : z4;

    *(float4*)&Xs[0][fm * GXS + fh] =
        make_float4(to_tf32(xa0.x), to_tf32(xa0.y), to_tf32(xa0.z), to_tf32(xa0.w));
    *(float4*)&Xs[0][fm * GXS + fh + 4] =
        make_float4(to_tf32(xa1.x), to_tf32(xa1.y), to_tf32(xa1.z), to_tf32(xa1.w));
    *(float4*)&Ws[0][fk * GWS + fn] =
        make_float4(to_tf32(wa0.x), to_tf32(wa0.y), to_tf32(wa0.z), to_tf32(wa0.w));
    *(float4*)&Ws[0][(fk + 8) * GWS + fn] =
        make_float4(to_tf32(wa1.x), to_tf32(wa1.y), to_tf32(wa1.z), to_tf32(wa1.w));

    int p = 0;
    for (int k0 = 0; k0 < K; k0 += 16) {
        __syncthreads();
        const bool more = (k0 + 16) < K;
        if (more) {
            xa0 = *(const float4*)&Xr[k0 + 16];
            xa1 = *(const float4*)&Xr[k0 + 20];
            wa0 = wok ? *(const float4*)&Wr[(size_t)(k0 + 16) * N] : z4;
            wa1 = wok ? *(const float4*)&Wr[(size_t)(k0 + 24) * N] : z4;
        }
#pragma unroll
        for (int ks = 0; ks < 2; ks++) {
            unsigned a[4][4];
#pragma unroll
            for (int mt = 0; mt < 4; mt++)
                ldsm4(a[mt], &Xs[p][(wm + mt * 16 + ar) * GXS + ks * 8 + ac]);
#pragma unroll
            for (int nt = 0; nt < 4; nt++) {
                unsigned bb[2];
                bb[0] = fu(Ws[p][(ks * 8 + qd) * GWS + wn + nt * 8 + g]);
                bb[1] = fu(Ws[p][(ks * 8 + qd + 4) * GWS + wn + nt * 8 + g]);
#pragma unroll
                for (int mt = 0; mt < 4; mt++) mma8(acc[mt][nt], a[mt], bb);
            }
        }
        if (more) {
            int q = p ^ 1;
            *(float4*)&Xs[q][fm * GXS + fh] = make_float4(
                to_tf32(xa0.x), to_tf32(xa0.y), to_tf32(xa0.z), to_tf32(xa0.w));
            *(float4*)&Xs[q][fm * GXS + fh + 4] = make_float4(
                to_tf32(xa1.x), to_tf32(xa1.y), to_tf32(xa1.z), to_tf32(xa1.w));
            *(float4*)&Ws[q][fk * GWS + fn] = make_float4(
                to_tf32(wa0.x), to_tf32(wa0.y), to_tf32(wa0.z), to_tf32(wa0.w));
            *(float4*)&Ws[q][(fk + 8) * GWS + fn] = make_float4(
                to_tf32(wa1.x), to_tf32(wa1.y), to_tf32(wa1.z), to_tf32(wa1.w));
        }
        p ^= 1;
    }

#pragma unroll
    for (int mt = 0; mt < 4; mt++)
#pragma unroll
        for (int nt = 0; nt < 4; nt++) {
            int row = m0 + wm + mt * 16 + g;
            int col = n0 + wn + nt * 8 + 2 * qd;
            if (col < N) {
                *(float2*)&C[(size_t)row * N + col] =
                    make_float2(acc[mt][nt][0], acc[mt][nt][1]);
                *(float2*)&C[(size_t)(row + 8) * N + col] =
                    make_float2(acc[mt][nt][2], acc[mt][nt][3]);
            }
        }
}

__global__ __launch_bounds__(256, 2) void gemm_k(const float* __restrict__ X,
                                                 const float* __restrict__ W,
                                                 float* __restrict__ C, int N,
                                                 int K) {
    gemm3(X, W, C, N, K, blockIdx.y * 128, blockIdx.x * 128);
}

__global__ __launch_bounds__(256, 2) void proj_k(
    const float* __restrict__ q, const float* __restrict__ k,
    const float* __restrict__ v, const float* __restrict__ WAq,
    const float* __restrict__ WBq, const float* __restrict__ WAk,
    const float* __restrict__ WBk, const float* __restrict__ WAv,
    const float* __restrict__ WBv) {
    const int slot = blockIdx.x;
    const int slot_seg[8] = {0, 1, 1, 1, 2, 3, 4, 5};
    const int slot_n0[8] = {0, 0, 128, 256, 0, 0, 0, 0};
    const int seg = slot_seg[slot];
    const int seg_N[6] = {96, 384, 32, 128, 32, 128};
    const float* Xp = (seg < 2) ? q : (seg < 4) ? k : v;
    const float* Wp;
    float* Cp;
    switch (seg) {
        case 0: Wp = WAq; Cp = g_Aq; break;
        case 1: Wp = WBq; Cp = g_Bq; break;
        case 2: Wp = WAk; Cp = g_Ak; break;
        case 3: Wp = WBk; Cp = g_Bk; break;
        case 4: Wp = WAv; Cp = g_Av; break;
        default: Wp = WBv; Cp = g_Bv; break;
    }
    gemm3(Xp, Wp, Cp, seg_N[seg], ND, blockIdx.y * 128, slot_n0[slot]);
}

// ---------------------------------------------------------------------------
// RoPE + rank contraction -> qh/kh/vh (b,h,s,d), tf32-rounded.
// qh additionally folds log2(e) so attention can use raw ex2.
// ---------------------------------------------------------------------------
__global__ __launch_bounds__(128) void mix_k() {
    const int t = blockIdx.x;
    const int b = t >> 11;
    const int s = t & (NS - 1);
    const int tid = threadIdx.x;

    __shared__ float sAq[96], sAk[32], sAv[32];
    __shared__ float sBq[384], sBk[128], sBv[128];

    if (tid < 96) sAq[tid] = g_Aq[t * 96 + tid];
    if (tid < 32) {
        sAk[tid] = g_Ak[t * 32 + tid];
        sAv[tid] = g_Av[t * 32 + tid];
    }
    for (int i = tid; i < 384; i += 128) sBq[i] = g_Bq[t * 384 + i];
    sBk[tid] = g_Bk[t * 128 + tid];
    sBv[tid] = g_Bv[t * 128 + tid];
    __syncthreads();

    for (int i = tid; i < (QR + RK) * 32; i += 128) {
        int r = i >> 5, dd = i & 31;
        float inv = (float)pow(10000.0, -(double)dd / 32.0);
        float c, sn;
        sincosf((float)s * inv, &sn, &c);
        float* base = (r < QR) ? &sBq[r * DKH] : &sBk[(r - QR) * DKH];
        float x1 = base[dd], x2 = base[dd + 32];
        base[dd] = x1 * c + x2 * sn;
        base[dd + 32] = -x1 * sn + x2 * c;
    }
    __syncthreads();

    const float qsc = 1.4426950408889634f / (6.f * 64.f);  // log2(e)/(QR*DK)
    for (int i = tid; i < NH * DKH; i += 128) {
        int h = i >> 6, d = i & 63;
        float aq = 0.f;
#pragma unroll
        for (int r = 0; r < QR; r++) aq += sAq[h * QR + r] * sBq[r * DKH + d];
        size_t o = (((size_t)b * NH + h) * NS + s) * DKH + d;
        g_qh[o] = to_tf32(aq * qsc);
        g_kh[o] = to_tf32((sAk[h * RK] * sBk[d] + sAk[h * RK + 1] * sBk[DKH + d]) * 0.5f);
        g_vh[o] = to_tf32((sAv[h * RK] * sBv[d] + sAv[h * RK + 1] * sBv[DKH + d]) * 0.5f);
    }
}

// ---------------------------------------------------------------------------
// V transpose: g_vh (b,h,s,d) -> g_vhT (b,h,d,s).
// ---------------------------------------------------------------------------
__global__ __launch_bounds__(256) void vtr_k() {
    __shared__ float t[32][33];
    const int bh = blockIdx.z;
    const float* src = g_vh + (size_t)bh * NS * DKH;
    float* dst = g_vhT + (size_t)bh * NS * DKH;
    const int s0 = blockIdx.x * 32, d0 = blockIdx.y * 32;
    const int tx = threadIdx.x, ty = threadIdx.y;
#pragma unroll
    for (int j = 0; j < 32; j += 8)
        t[ty + j][tx] = src[(size_t)(s0 + ty + j) * DKH + d0 + tx];
    __syncthreads();
#pragma unroll
    for (int j = 0; j < 32; j += 8)
        dst[(size_t)(d0 + ty + j) * NS + s0 + tx] = t[tx][ty + j];
}

// ---------------------------------------------------------------------------
// Causal flash attention, fixed-max softmax with log2e folded into Q.
// Q tile 128 (8 warps x 16 rows), KV tile 64 processed in 4 chunks of 16 keys:
// S-chunk mma -> mask -> ex2 -> STS into per-warp double-buffered P scratch ->
// ldmatrix A-frags -> PV mma. No shuffles in the P path.
// Smem = KV double-buffer 69.6KB + P scratch 20KB = 88KB -> 2 blocks/SM.
// ---------------------------------------------------------------------------
#define KS_STR 68
#define VTS 68
#define PBS 20
#define KV_STAGE (64 * KS_STR + 64 * VTS)
#define PB_WARP (16 * PBS)
#define ATT_SMEM ((2 * KV_STAGE + 8 * 2 * PB_WARP) * (int)sizeof(float))

__global__ __launch_bounds__(256, 2) void attn_k() {
    extern __shared__ float sm[];

    const int qt = gridDim.x - 1 - blockIdx.x;  // heavy tiles first
    const int h = blockIdx.y, b = blockIdx.z;
    const int q0 = qt * 128;
    const int tid = threadIdx.x, lane = tid & 31, wid = tid >> 5;
    const int g = lane >> 2, qd = lane & 3;
    const size_t bh = ((size_t)b * NH + h) * NS * DKH;
    const int rb = wid * 16;
    const int ar = (lane & 7) + ((lane >> 3) & 1) * 8, ac = (lane >> 4) * 4;
    float* const Pw = sm + 2 * KV_STAGE + wid * 2 * PB_WARP;  // per-warp scratch

    const int frow = tid >> 4, fc4 = (tid & 15) * 4;

    unsigned qa[8][4];
    {
        const float* Q0 = &g_qh[bh + (size_t)(q0 + rb + g) * DKH];
        const float* Q1 = Q0 + 8 * DKH;
#pragma unroll
        for (int ks = 0; ks < 8; ks++) {
            qa[ks][0] = fu(Q0[ks * 8 + qd]);
            qa[ks][1] = fu(Q1[ks * 8 + qd]);
            qa[ks][2] = fu(Q0[ks * 8 + qd + 4]);
            qa[ks][3] = fu(Q1[ks * 8 + qd + 4]);
        }
    }

    float l2[2] = {0.f, 0.f};  // per-lane partial row sums
    float o[8][4];
#pragma unroll
    for (int nt = 0; nt < 8; nt++)
#pragma unroll
        for (int j = 0; j < 4; j++) o[nt][j] = 0.f;

    const int nkt = 2 * qt + 2;

    {  // prime stage 0 with tile kt=0
        float* Ksp = sm;
        float* Vsp = sm + 64 * KS_STR;
#pragma unroll
        for (int j = 0; j < 4; j++) {
            int row = frow + j * 16;
            cpa16(&Ksp[row * KS_STR + fc4], &g_kh[bh + (size_t)row * DKH + fc4]);
            cpa16(&Vsp[row * VTS + fc4], &g_vhT[bh + (size_t)row * NS + fc4]);
        }
        CP_COMMIT();
    }

    for (int kt = 0; kt < nkt; kt++) {
        const int p = kt & 1;
        float* Ksp = sm + p * KV_STAGE;
        float* Vsp = Ksp + 64 * KS_STR;

        CP_WAIT0();
        __syncthreads();

        if (kt + 1 < nkt) {
            float* Ksn = sm + (p ^ 1) * KV_STAGE;
            float* Vsn = Ksn + 64 * KS_STR;
#pragma unroll
            for (int j = 0; j < 4; j++) {
                int row = frow + j * 16;
                cpa16(&Ksn[row * KS_STR + fc4],
                      &g_kh[bh + (size_t)((kt + 1) * 64 + row) * DKH + fc4]);
                cpa16(&Vsn[row * VTS + fc4],
                      &g_vhT[bh + (size_t)row * NS + (kt + 1) * 64 + fc4]);
            }
            CP_COMMIT();
        }

        if (!((kt == 2 * qt + 1) && (wid < 4))) {
            const bool diag = (kt >= 2 * qt);
#pragma unroll
            for (int kc = 0; kc < 4; kc++) {  // 16-key chunks
                float s[2][4];
#pragma unroll
                for (int t = 0; t < 2; t++)
#pragma unroll
                    for (int j = 0; j < 4; j++) s[t][j] = 0.f;

                // S chunk: 16 keys x 64 d
#pragma unroll
                for (int ks = 0; ks < 8; ks++) {
                    unsigned kb[4];
                    ldsm4(kb, &Ksp[(kc * 16 + ar) * KS_STR + ks * 8 + ac]);
                    unsigned b0[2] = {kb[0], kb[2]}, b1[2] = {kb[1], kb[3]};
                    mma8(s[0], qa[ks], b0);
                    mma8(s[1], qa[ks], b1);
                }

                if (diag) {
#pragma unroll
                    for (int t = 0; t < 2; t++)
#pragma unroll
                        for (int j = 0; j < 4; j++) {
                            int col = kt * 64 + kc * 16 + t * 8 + 2 * qd + (j & 1);
                            int row = q0 + rb + g + (j >> 1) * 8;
                            if (col > row) s[t][j] = -1e30f;
                        }
                }

                // weights = 2^s (log2e pre-folded); tf32-round; accumulate l
#pragma unroll
                for (int t = 0; t < 2; t++)
#pragma unroll
                    for (int j = 0; j < 4; j++) s[t][j] = to_tf32(ex2(s[t][j]));
                l2[0] += s[0][0] + s[0][1] + s[1][0] + s[1][1];
                l2[1] += s[0][2] + s[0][3] + s[1][2] + s[1][3];

                // store P chunk to per-warp scratch (double-buffered)
                float* Pb = Pw + (kc & 1) * PB_WARP;
#pragma unroll
                for (int t = 0; t < 2; t++) {
                    *(float2*)&Pb[g * PBS + t * 8 + 2 * qd] =
                        make_float2(s[t][0], s[t][1]);
                    *(float2*)&Pb[(g + 8) * PBS + t * 8 + 2 * qd] =
                        make_float2(s[t][2], s[t][3]);
                }
                __syncwarp();

                // P A-frags via ldmatrix (16 q rows x 16 keys)
                unsigned pa[2][4];
                ldsm4(pa[0], &Pb[ar * PBS + ac]);
                ldsm4(pa[1], &Pb[ar * PBS + 8 + ac]);

                // PV: o += P_chunk @ V[kc*16 .. +16][:]
#pragma unroll
                for (int hf = 0; hf < 2; hf++) {
#pragma unroll
                    for (int dt = 0; dt < 4; dt++) {
                        unsigned vb[4];
                        ldsm4(vb, &Vsp[(dt * 16 + ar) * VTS + kc * 16 + hf * 8 + ac]);
                        unsigned b0[2] = {vb[0], vb[2]}, b1[2] = {vb[1], vb[3]};
                        mma8(o[2 * dt], pa[hf], b0);
                        mma8(o[2 * dt + 1], pa[hf], b1);
                    }
                }
            }
        }
    }

    // reduce l across the quad (once), normalize, store
    l2[0] += __shfl_xor_sync(0xffffffffu, l2[0], 1);
    l2[0] += __shfl_xor_sync(0xffffffffu, l2[0], 2);
    l2[1] += __shfl_xor_sync(0xffffffffu, l2[1], 1);
    l2[1] += __shfl_xor_sync(0xffffffffu, l2[1], 2);

#pragma unroll
    for (int half = 0; half < 2; half++) {
        int jo = half * 2;
        float inv = 1.f / l2[half];
        int row = q0 + rb + g + half * 8;
        size_t ob = (((size_t)b * NS + row) * NH + h) * DKH;
#pragma unroll
        for (int nt = 0; nt < 8; nt++) {
            int col = nt * 8 + 2 * qd;
            *(float2*)&g_att[ob + col] =
                make_float2(o[nt][jo] * inv, o[nt][jo + 1] * inv);
        }
    }
}

// ---------------------------------------------------------------------------
extern "C" void kernel_launch(void* const* d_in, const int* in_sizes, int n_in,
                              void* d_out, int out_size) {
    (void)in_sizes; (void)n_in; (void)out_size;
    const float* q = (const float*)d_in[0];
    const float* k = (const float*)d_in[1];
    const float* v = (const float*)d_in[2];
    const float* W_Aq = (const float*)d_in[4];
    const float* W_Ak = (const float*)d_in[5];
    const float* W_Av = (const float*)d_in[6];
    const float* W_Bq = (const float*)d_in[7];
    const float* W_Bk = (const float*)d_in[8];
    const float* W_Bv = (const float*)d_in[9];
    const float* Wo = (const float*)d_in[10];

    float* pAtt;
    cudaGetSymbolAddress((void**)&pAtt, g_att);

    proj_k<<<dim3(8, 32), 256>>>(q, k, v, W_Aq, W_Bq, W_Ak, W_Bk, W_Av, W_Bv);
    mix_k<<<NT, 128>>>();
    vtr_k<<<dim3(NS / 32, DKH / 32, NB * NH), dim3(32, 8)>>>();
    cudaFuncSetAttribute(attn_k, cudaFuncAttributeMaxDynamicSharedMemorySize,
                         ATT_SMEM);
    attn_k<<<dim3(NS / 128, NH, NB), 256, ATT_SMEM>>>();
    gemm_k<<<dim3(ND / 128, NT / 128), 256>>>(pAtt, Wo, (float*)d_out, ND, ND);
}

// round 14
// speedup vs baseline: 1.1979x; 1.1979x over previous
#include <cuda_runtime.h>

#define NB 2
#define NS 2048
#define ND 1024
#define NH 16
#define DKH 64
#define QR 6
#define RK 2
#define NT (NB * NS)

__device__ float g_Aq[NT * 96];
__device__ float g_Bq[NT * 384];
__device__ float g_Ak[NT * 32];
__device__ float g_Bk[NT * 128];
__device__ float g_Av[NT * 32];
__device__ float g_Bv[NT * 128];
__device__ float g_qh[(size_t)NB * NH * NS * DKH];
__device__ float g_kh[(size_t)NB * NH * NS * DKH];
__device__ float g_vh[(size_t)NB * NH * NS * DKH];   // (b,h,s,d)
__device__ float g_vhT[(size_t)NB * NH * DKH * NS];  // (b,h,d,s)
__device__ float g_att[(size_t)NT * ND];

__device__ __forceinline__ float to_tf32(float x) {
    asm("cvt.rna.tf32.f32 %0, %0;" : "+f"(x));
    return x;
}
__device__ __forceinline__ float ex2(float x) {
    asm("ex2.approx.f32 %0, %0;" : "+f"(x));
    return x;
}
__device__ __forceinline__ unsigned fu(float x) { return __float_as_uint(x); }

__device__ __forceinline__ void mma8(float* c, const unsigned* a, const unsigned* b) {
    asm("mma.sync.aligned.m16n8k8.row.col.f32.tf32.tf32.f32 "
        "{%0,%1,%2,%3},{%4,%5,%6,%7},{%8,%9},{%0,%1,%2,%3};"
        : "+f"(c[0]), "+f"(c[1]), "+f"(c[2]), "+f"(c[3])
        : "r"(a[0]), "r"(a[1]), "r"(a[2]), "r"(a[3]), "r"(b[0]), "r"(b[1]));
}

__device__ __forceinline__ void ldsm4(unsigned* r, const float* p) {
    unsigned a = (unsigned)__cvta_generic_to_shared(p);
    asm volatile("ldmatrix.sync.aligned.m8n8.x4.shared.b16 {%0,%1,%2,%3},[%4];"
                 : "=r"(r[0]), "=r"(r[1]), "=r"(r[2]), "=r"(r[3]) : "r"(a));
}

__device__ __forceinline__ void cpa16(float* s, const float* g) {
    unsigned sa = (unsigned)__cvta_generic_to_shared(s);
    asm volatile("cp.async.cg.shared.global [%0],[%1],16;" ::"r"(sa), "l"(g));
}
#define CP_COMMIT() asm volatile("cp.async.commit_group;")
#define CP_WAIT0() asm volatile("cp.async.wait_group 0;" ::: "memory")

// ---------------------------------------------------------------------------
// tf32 GEMM: C[m0:+128, n0:+128] = X[M,K]*W[K,N]. 8 warps (2m x 4n),
// warp tile 64x32, BK=16, ldmatrix A-frags, double-buffered smem.
// ---------------------------------------------------------------------------
#define GXS 20
#define GWS 136

__device__ __forceinline__ void gemm3(const float* __restrict__ X,
                                      const float* __restrict__ W,
                                      float* __restrict__ C, int N, int K,
                                      int m0, int n0) {
    __shared__ float Xs[2][128 * GXS];
    __shared__ float Ws[2][16 * GWS];
    const int tid = threadIdx.x, lane = tid & 31, wid = tid >> 5;
    const int g = lane >> 2, qd = lane & 3;
    const int wm = (wid & 1) * 64, wn = (wid >> 1) * 32;
    const int ar = (lane & 7) + ((lane >> 3) & 1) * 8, ac = (lane >> 4) * 4;

    const int fm = tid >> 1, fh = (tid & 1) * 8;
    const int fk = tid >> 5, fn = (tid & 31) * 4;
    const bool wok = (n0 + fn) < N;
    const float* Xr = X + (size_t)(m0 + fm) * K + fh;
    const float* Wr = W + (size_t)fk * N + n0 + fn;

    float acc[4][4][4];
#pragma unroll
    for (int mt = 0; mt < 4; mt++)
#pragma unroll
        for (int nt = 0; nt < 4; nt++)
#pragma unroll
            for (int j = 0; j < 4; j++) acc[mt][nt][j] = 0.f;

    const float4 z4 = make_float4(0.f, 0.f, 0.f, 0.f);
    float4 xa0 = *(const float4*)&Xr[0];
    float4 xa1 = *(const float4*)&Xr[4];
    float4 wa0 = wok ? *(const float4*)&Wr[0] : z4;
    float4 wa1 = wok ? *(const float4*)&Wr[(size_t)8 * N] : z4;

    *(float4*)&Xs[0][fm * GXS + fh] =
        make_float4(to_tf32(xa0.x), to_tf32(xa0.y), to_tf32(xa0.z), to_tf32(xa0.w));
    *(float4*)&Xs[0][fm * GXS + fh + 4] =
        make_float4(to_tf32(xa1.x), to_tf32(xa1.y), to_tf32(xa1.z), to_tf32(xa1.w));
    *(float4*)&Ws[0][fk * GWS + fn] =
        make_float4(to_tf32(wa0.x), to_tf32(wa0.y), to_tf32(wa0.z), to_tf32(wa0.w));
    *(float4*)&Ws[0][(fk + 8) * GWS + fn] =
        make_float4(to_tf32(wa1.x), to_tf32(wa1.y), to_tf32(wa1.z), to_tf32(wa1.w));

    int p = 0;
    for (int k0 = 0; k0 < K; k0 += 16) {
        __syncthreads();
        const bool more = (k0 + 16) < K;
        if (more) {
            xa0 = *(const float4*)&Xr[k0 + 16];
            xa1 = *(const float4*)&Xr[k0 + 20];
            wa0 = wok ? *(const float4*)&Wr[(size_t)(k0 + 16) * N] : z4;
            wa1 = wok ? *(const float4*)&Wr[(size_t)(k0 + 24) * N] : z4;
        }
#pragma unroll
        for (int ks = 0; ks < 2; ks++) {
            unsigned a[4][4];
#pragma unroll
            for (int mt = 0; mt < 4; mt++)
                ldsm4(a[mt], &Xs[p][(wm + mt * 16 + ar) * GXS + ks * 8 + ac]);
#pragma unroll
            for (int nt = 0; nt < 4; nt++) {
                unsigned bb[2];
                bb[0] = fu(Ws[p][(ks * 8 + qd) * GWS + wn + nt * 8 + g]);
                bb[1] = fu(Ws[p][(ks * 8 + qd + 4) * GWS + wn + nt * 8 + g]);
#pragma unroll
                for (int mt = 0; mt < 4; mt++) mma8(acc[mt][nt], a[mt], bb);
            }
        }
        if (more) {
            int q = p ^ 1;
            *(float4*)&Xs[q][fm * GXS + fh] = make_float4(
                to_tf32(xa0.x), to_tf32(xa0.y), to_tf32(xa0.z), to_tf32(xa0.w));
            *(float4*)&Xs[q][fm * GXS + fh + 4] = make_float4(
                to_tf32(xa1.x), to_tf32(xa1.y), to_tf32(xa1.z), to_tf32(xa1.w));
            *(float4*)&Ws[q][fk * GWS + fn] = make_float4(
                to_tf32(wa0.x), to_tf32(wa0.y), to_tf32(wa0.z), to_tf32(wa0.w));
            *(float4*)&Ws[q][(fk + 8) * GWS + fn] = make_float4(
                to_tf32(wa1.x), to_tf32(wa1.y), to_tf32(wa1.z), to_tf32(wa1.w));
        }
        p ^= 1;
    }

#pragma unroll
    for (int mt = 0; mt < 4; mt++)
#pragma unroll
        for (int nt = 0; nt < 4; nt++) {
            int row = m0 + wm + mt * 16 + g;
            int col = n0 + wn + nt * 8 + 2 * qd;
            if (col < N) {
                *(float2*)&C[(size_t)row * N + col] =
                    make_float2(acc[mt][nt][0], acc[mt][nt][1]);
                *(float2*)&C[(size_t)(row + 8) * N + col] =
                    make_float2(acc[mt][nt][2], acc[mt][nt][3]);
            }
        }
}

__global__ __launch_bounds__(256, 2) void gemm_k(const float* __restrict__ X,
                                                 const float* __restrict__ W,
                                                 float* __restrict__ C, int N,
                                                 int K) {
    gemm3(X, W, C, N, K, blockIdx.y * 128, blockIdx.x * 128);
}

__global__ __launch_bounds__(256, 2) void proj_k(
    const float* __restrict__ q, const float* __restrict__ k,
    const float* __restrict__ v, const float* __restrict__ WAq,
    const float* __restrict__ WBq, const float* __restrict__ WAk,
    const float* __restrict__ WBk, const float* __restrict__ WAv,
    const float* __restrict__ WBv) {
    const int slot = blockIdx.x;
    const int slot_seg[8] = {0, 1, 1, 1, 2, 3, 4, 5};
    const int slot_n0[8] = {0, 0, 128, 256, 0, 0, 0, 0};
    const int seg = slot_seg[slot];
    const int seg_N[6] = {96, 384, 32, 128, 32, 128};
    const float* Xp = (seg < 2) ? q : (seg < 4) ? k : v;
    const float* Wp;
    float* Cp;
    switch (seg) {
        case 0: Wp = WAq; Cp = g_Aq; break;
        case 1: Wp = WBq; Cp = g_Bq; break;
        case 2: Wp = WAk; Cp = g_Ak; break;
        case 3: Wp = WBk; Cp = g_Bk; break;
        case 4: Wp = WAv; Cp = g_Av; break;
        default: Wp = WBv; Cp = g_Bv; break;
    }
    gemm3(Xp, Wp, Cp, seg_N[seg], ND, blockIdx.y * 128, slot_n0[slot]);
}

// ---------------------------------------------------------------------------
// RoPE + rank contraction -> qh/kh/vh (b,h,s,d), tf32-rounded.
// qh folds log2(e); inv_freq via fp32 exp2f (NOT double pow: FP64 pipe).
// ---------------------------------------------------------------------------
__global__ __launch_bounds__(128) void mix_k() {
    const int t = blockIdx.x;
    const int b = t >> 11;
    const int s = t & (NS - 1);
    const int tid = threadIdx.x;

    __shared__ float sAq[96], sAk[32], sAv[32];
    __shared__ float sBq[384], sBk[128], sBv[128];

    if (tid < 96) sAq[tid] = g_Aq[t * 96 + tid];
    if (tid < 32) {
        sAk[tid] = g_Ak[t * 32 + tid];
        sAv[tid] = g_Av[t * 32 + tid];
    }
    for (int i = tid; i < 384; i += 128) sBq[i] = g_Bq[t * 384 + i];
    sBk[tid] = g_Bk[t * 128 + tid];
    sBv[tid] = g_Bv[t * 128 + tid];
    __syncthreads();

    for (int i = tid; i < (QR + RK) * 32; i += 128) {
        int r = i >> 5, dd = i & 31;
        // inv_freq = 10000^(-dd/32) = 2^(-dd * log2(10000)/32), fp32 exp2f
        float inv = exp2f(-0.41524101186092029f * (float)dd);
        float c, sn;
        sincosf((float)s * inv, &sn, &c);
        float* base = (r < QR) ? &sBq[r * DKH] : &sBk[(r - QR) * DKH];
        float x1 = base[dd], x2 = base[dd + 32];
        base[dd] = x1 * c + x2 * sn;
        base[dd + 32] = -x1 * sn + x2 * c;
    }
    __syncthreads();

    const float qsc = 1.4426950408889634f / (6.f * 64.f);  // log2(e)/(QR*DK)
    for (int i = tid; i < NH * DKH; i += 128) {
        int h = i >> 6, d = i & 63;
        float aq = 0.f;
#pragma unroll
        for (int r = 0; r < QR; r++) aq += sAq[h * QR + r] * sBq[r * DKH + d];
        size_t o = (((size_t)b * NH + h) * NS + s) * DKH + d;
        g_qh[o] = to_tf32(aq * qsc);
        g_kh[o] = to_tf32((sAk[h * RK] * sBk[d] + sAk[h * RK + 1] * sBk[DKH + d]) * 0.5f);
        g_vh[o] = to_tf32((sAv[h * RK] * sBv[d] + sAv[h * RK + 1] * sBv[DKH + d]) * 0.5f);
    }
}

// ---------------------------------------------------------------------------
// V transpose: g_vh (b,h,s,d) -> g_vhT (b,h,d,s).
// ---------------------------------------------------------------------------
__global__ __launch_bounds__(256) void vtr_k() {
    __shared__ float t[32][33];
    const int bh = blockIdx.z;
    const float* src = g_vh + (size_t)bh * NS * DKH;
    float* dst = g_vhT + (size_t)bh * NS * DKH;
    const int s0 = blockIdx.x * 32, d0 = blockIdx.y * 32;
    const int tx = threadIdx.x, ty = threadIdx.y;
#pragma unroll
    for (int j = 0; j < 32; j += 8)
        t[ty + j][tx] = src[(size_t)(s0 + ty + j) * DKH + d0 + tx];
    __syncthreads();
#pragma unroll
    for (int j = 0; j < 32; j += 8)
        dst[(size_t)(d0 + ty + j) * NS + s0 + tx] = t[tx][ty + j];
}

// ---------------------------------------------------------------------------
// Causal flash attention, fixed-max softmax (log2e folded into Q), hybrid
// phase structure: full 64-key S phase (8 independent mma chains) -> ex2 ->
// one 16x64 P store per warp -> 1 syncwarp -> full PV phase (P and V^T frags
// both via ldmatrix.x4, 8 independent chains).
// Smem = KV double-buffer 69.6KB + per-warp P 34.8KB = 102KB -> 2 blocks/SM.
// ---------------------------------------------------------------------------
#define KS_STR 68
#define VTS 68
#define PPS 68
#define KV_STAGE (64 * KS_STR + 64 * VTS)
#define PB_WARP (16 * PPS)
#define ATT_SMEM ((2 * KV_STAGE + 8 * PB_WARP) * (int)sizeof(float))

__global__ __launch_bounds__(256, 2) void attn_k() {
    extern __shared__ float sm[];

    const int qt = gridDim.x - 1 - blockIdx.x;  // heavy tiles first
    const int h = blockIdx.y, b = blockIdx.z;
    const int q0 = qt * 128;
    const int tid = threadIdx.x, lane = tid & 31, wid = tid >> 5;
    const int g = lane >> 2, qd = lane & 3;
    const size_t bh = ((size_t)b * NH + h) * NS * DKH;
    const int rb = wid * 16;
    const int ar = (lane & 7) + ((lane >> 3) & 1) * 8, ac = (lane >> 4) * 4;
    float* const Pw = sm + 2 * KV_STAGE + wid * PB_WARP;  // per-warp P scratch

    const int frow = tid >> 4, fc4 = (tid & 15) * 4;

    unsigned qa[8][4];
    {
        const float* Q0 = &g_qh[bh + (size_t)(q0 + rb + g) * DKH];
        const float* Q1 = Q0 + 8 * DKH;
#pragma unroll
        for (int ks = 0; ks < 8; ks++) {
            qa[ks][0] = fu(Q0[ks * 8 + qd]);
            qa[ks][1] = fu(Q1[ks * 8 + qd]);
            qa[ks][2] = fu(Q0[ks * 8 + qd + 4]);
            qa[ks][3] = fu(Q1[ks * 8 + qd + 4]);
        }
    }

    float l2[2] = {0.f, 0.f};  // per-lane partial row sums
    float o[8][4];
#pragma unroll
    for (int nt = 0; nt < 8; nt++)
#pragma unroll
        for (int j = 0; j < 4; j++) o[nt][j] = 0.f;

    const int nkt = 2 * qt + 2;

    {  // prime stage 0 with tile kt=0
        float* Ksp = sm;
        float* Vsp = sm + 64 * KS_STR;
#pragma unroll
        for (int j = 0; j < 4; j++) {
            int row = frow + j * 16;
            cpa16(&Ksp[row * KS_STR + fc4], &g_kh[bh + (size_t)row * DKH + fc4]);
            cpa16(&Vsp[row * VTS + fc4], &g_vhT[bh + (size_t)row * NS + fc4]);
        }
        CP_COMMIT();
    }

    for (int kt = 0; kt < nkt; kt++) {
        const int p = kt & 1;
        float* Ksp = sm + p * KV_STAGE;
        float* Vsp = Ksp + 64 * KS_STR;

        CP_WAIT0();
        __syncthreads();

        if (kt + 1 < nkt) {
            float* Ksn = sm + (p ^ 1) * KV_STAGE;
            float* Vsn = Ksn + 64 * KS_STR;
#pragma unroll
            for (int j = 0; j < 4; j++) {
                int row = frow + j * 16;
                cpa16(&Ksn[row * KS_STR + fc4],
                      &g_kh[bh + (size_t)((kt + 1) * 64 + row) * DKH + fc4]);
                cpa16(&Vsn[row * VTS + fc4],
                      &g_vhT[bh + (size_t)row * NS + (kt + 1) * 64 + fc4]);
            }
            CP_COMMIT();
        }

        if (!((kt == 2 * qt + 1) && (wid < 4))) {
            // ---- S phase: 16 q rows x 64 keys, 8 independent acc pairs ----
            float s[8][4];
#pragma unroll
            for (int nt = 0; nt < 8; nt++)
#pragma unroll
                for (int j = 0; j < 4; j++) s[nt][j] = 0.f;
#pragma unroll
            for (int ks = 0; ks < 8; ks++) {
#pragma unroll
                for (int pp = 0; pp < 4; pp++) {
                    unsigned kb[4];
                    ldsm4(kb, &Ksp[(pp * 16 + ar) * KS_STR + ks * 8 + ac]);
                    unsigned b0[2] = {kb[0], kb[2]}, b1[2] = {kb[1], kb[3]};
                    mma8(s[2 * pp], qa[ks], b0);
                    mma8(s[2 * pp + 1], qa[ks], b1);
                }
            }

            if (kt >= 2 * qt) {  // causal mask on diagonal tiles
#pragma unroll
                for (int nt = 0; nt < 8; nt++)
#pragma unroll
                    for (int j = 0; j < 4; j++) {
                        int col = kt * 64 + nt * 8 + 2 * qd + (j & 1);
                        int row = q0 + rb + g + (j >> 1) * 8;
                        if (col > row) s[nt][j] = -1e30f;
                    }
            }

            // weights = 2^s; tf32-round; accumulate per-lane partial sums
#pragma unroll
            for (int nt = 0; nt < 8; nt++) {
#pragma unroll
                for (int j = 0; j < 4; j++) s[nt][j] = to_tf32(ex2(s[nt][j]));
                l2[0] += s[nt][0] + s[nt][1];
                l2[1] += s[nt][2] + s[nt][3];
            }

            // store full 16x64 P tile to per-warp scratch
#pragma unroll
            for (int nt = 0; nt < 8; nt++) {
                *(float2*)&Pw[g * PPS + nt * 8 + 2 * qd] =
                    make_float2(s[nt][0], s[nt][1]);
                *(float2*)&Pw[(g + 8) * PPS + nt * 8 + 2 * qd] =
                    make_float2(s[nt][2], s[nt][3]);
            }
            __syncwarp();

            // ---- PV phase: P A-frags + V^T B-frags via ldmatrix ----
#pragma unroll
            for (int ks = 0; ks < 8; ks++) {
                unsigned pa[4];
                ldsm4(pa, &Pw[ar * PPS + ks * 8 + ac]);
#pragma unroll
                for (int dt = 0; dt < 4; dt++) {
                    unsigned vb[4];
                    ldsm4(vb, &Vsp[(dt * 16 + ar) * VTS + ks * 8 + ac]);
                    unsigned b0[2] = {vb[0], vb[2]}, b1[2] = {vb[1], vb[3]};
                    mma8(o[2 * dt], pa, b0);
                    mma8(o[2 * dt + 1], pa, b1);
                }
            }
            __syncwarp();  // P reads done before next kt's stores
        }
    }

    // reduce l across the quad (once), normalize, store
    l2[0] += __shfl_xor_sync(0xffffffffu, l2[0], 1);
    l2[0] += __shfl_xor_sync(0xffffffffu, l2[0], 2);
    l2[1] += __shfl_xor_sync(0xffffffffu, l2[1], 1);
    l2[1] += __shfl_xor_sync(0xffffffffu, l2[1], 2);

#pragma unroll
    for (int half = 0; half < 2; half++) {
        int jo = half * 2;
        float inv = 1.f / l2[half];
        int row = q0 + rb + g + half * 8;
        size_t ob = (((size_t)b * NS + row) * NH + h) * DKH;
#pragma unroll
        for (int nt = 0; nt < 8; nt++) {
            int col = nt * 8 + 2 * qd;
            *(float2*)&g_att[ob + col] =
                make_float2(o[nt][jo] * inv, o[nt][jo + 1] * inv);
        }
    }
}

// ---------------------------------------------------------------------------
extern "C" void kernel_launch(void* const* d_in, const int* in_sizes, int n_in,
                              void* d_out, int out_size) {
    (void)in_sizes; (void)n_in; (void)out_size;
    const float* q = (const float*)d_in[0];
    const float* k = (const float*)d_in[1];
    const float* v = (const float*)d_in[2];
    const float* W_Aq = (const float*)d_in[4];
    const float* W_Ak = (const float*)d_in[5];
    const float* W_Av = (const float*)d_in[6];
    const float* W_Bq = (const float*)d_in[7];
    const float* W_Bk = (const float*)d_in[8];
    const float* W_Bv = (const float*)d_in[9];
    const float* Wo = (const float*)d_in[10];

    float* pAtt;
    cudaGetSymbolAddress((void**)&pAtt, g_att);

    proj_k<<<dim3(8, 32), 256>>>(q, k, v, W_Aq, W_Bq, W_Ak, W_Bk, W_Av, W_Bv);
    mix_k<<<NT, 128>>>();
    vtr_k<<<dim3(NS / 32, DKH / 32, NB * NH), dim3(32, 8)>>>();
    cudaFuncSetAttribute(attn_k, cudaFuncAttributeMaxDynamicSharedMemorySize,
                         ATT_SMEM);
    attn_k<<<dim3(NS / 128, NH, NB), 256, ATT_SMEM>>>();
    gemm_k<<<dim3(ND / 128, NT / 128), 256>>>(pAtt, Wo, (float*)d_out, ND, ND);
}